// round 7
// baseline (speedup 1.0000x reference)
#include <cuda_runtime.h>
#include <cuda_bf16.h>
#include <cstdint>

// Problem dims
constexpr int kB  = 16;
constexpr int kN  = 128;
constexpr int kC  = 512;
constexpr int kH  = 8;
constexpr int kR  = 17;
constexpr int kHD = 64;
constexpr int kBN = kB * kN;    // 2048
constexpr int kKp = 3 * kC;     // 1536 split-K' (c contraction)
constexpr int kKq = 3 * kHD;    // 192 split-K' (d contraction, qk)
constexpr int kKm = 3 * kN;     // 384 split-K' (m contraction, av)

// Scratch (device globals; no allocations allowed)
__device__ float g_S[kB * kH * kN * kN]; // 8 MB  (pre-scaled by 0.125)
__device__ int   g_mask_mode;
__device__ __nv_bfloat16 g_Ax[kBN * kKp];        // x hi|lo|hi
__device__ __nv_bfloat16 g_Bqkv[kKp * kKp];      // [q_w;kv_w] hi|hi|lo
__device__ __nv_bfloat16 g_Bproj[kC * kKp];      // proj_w hi|hi|lo
__device__ __nv_bfloat16 g_AO[kBN * kKp];        // O hi|lo|hi (from av epilogue)
__device__ __nv_bfloat16 g_qbf[kB * kH * kN * kKq]; // q hi|lo|hi per (b,h)
__device__ __nv_bfloat16 g_kbf[kB * kH * kN * kKq]; // k hi|hi|lo per (b,h)
__device__ __nv_bfloat16 g_W3[kB * kH * kN * kKm];  // W hi|lo|hi: [bh][n][384]
__device__ __nv_bfloat16 g_yv3[kB * kH * kHD * kKm];// yv hi|hi|lo: [bh][d][384]

__device__ __forceinline__ float neg_inf() { return __int_as_float(0xFF800000); }

// ===================== baseline-PTX helpers =====================
__device__ __forceinline__ uint32_t smem_u32(const void* p) {
    uint32_t a;
    asm("{ .reg .u64 t; cvta.to.shared.u64 t, %1; cvt.u32.u64 %0, t; }"
        : "=r"(a) : "l"(p));
    return a;
}
__device__ __forceinline__ void cp_async16(uint32_t saddr, const void* gaddr) {
    asm volatile("cp.async.cg.shared.global [%0], [%1], 16;"
                 :: "r"(saddr), "l"(gaddr) : "memory");
}
__device__ __forceinline__ void cp_commit() {
    asm volatile("cp.async.commit_group;" ::: "memory");
}
__device__ __forceinline__ void cp_wait0() {
    asm volatile("cp.async.wait_group 0;" ::: "memory");
}
__device__ __forceinline__ void ldsm_x4(uint32_t* r, uint32_t addr) {
    asm volatile("ldmatrix.sync.aligned.m8n8.x4.shared.b16 {%0,%1,%2,%3}, [%4];"
                 : "=r"(r[0]), "=r"(r[1]), "=r"(r[2]), "=r"(r[3]) : "r"(addr));
}
__device__ __forceinline__ void mma16816(float* d, const uint32_t* a, const uint32_t* b) {
    asm volatile("mma.sync.aligned.m16n8k16.row.col.f32.bf16.bf16.f32 "
                 "{%0,%1,%2,%3}, {%4,%5,%6,%7}, {%8,%9}, {%0,%1,%2,%3};"
                 : "+f"(d[0]), "+f"(d[1]), "+f"(d[2]), "+f"(d[3])
                 : "r"(a[0]), "r"(a[1]), "r"(a[2]), "r"(a[3]),
                   "r"(b[0]), "r"(b[1]));
}
__device__ __forceinline__ uint32_t pack_bf2(__nv_bfloat16 lo, __nv_bfloat16 hi) {
    return ((uint32_t)__bfloat16_as_ushort(hi) << 16) | __bfloat16_as_ushort(lo);
}

// ===================== fused converts + mask probe =====================
__global__ __launch_bounds__(128) void convert_all_kernel(
    const float* __restrict__ x, const float* __restrict__ q_w,
    const float* __restrict__ kv_w, const float* __restrict__ proj_w,
    const void* __restrict__ mask,
    __nv_bfloat16* __restrict__ Ax, __nv_bfloat16* __restrict__ Bqkv,
    __nv_bfloat16* __restrict__ Bproj)
{
    const int rb = blockIdx.x;
    if (rb == 4096) {
        __shared__ int s_not_i32, s_not_f32;
        if (threadIdx.x == 0) { s_not_i32 = 0; s_not_f32 = 0; }
        __syncthreads();
        const unsigned int* w = (const unsigned int*)mask;
        int bad_i = 0, bad_f = 0;
        for (int i = threadIdx.x; i < 544; i += 128) {
            unsigned int v = w[i];
            if (v > 1u) bad_i = 1;
            if (v != 0u && v != 0x3F800000u) bad_f = 1;
        }
        if (bad_i) atomicOr(&s_not_i32, 1);
        if (bad_f) atomicOr(&s_not_f32, 1);
        __syncthreads();
        if (threadIdx.x == 0)
            g_mask_mode = (!s_not_i32) ? 0 : ((!s_not_f32) ? 1 : 2);
        return;
    }
    const float* src;
    __nv_bfloat16* dst;
    bool aSide;
    if (rb < 2048)      { src = x + (size_t)rb * kC;             dst = Ax + (size_t)rb * kKp;           aSide = true;  }
    else if (rb < 2560) { int r = rb - 2048; src = q_w + (size_t)r * kC;    dst = Bqkv + (size_t)r * kKp;        aSide = false; }
    else if (rb < 3584) { int r = rb - 2560; src = kv_w + (size_t)r * kC;   dst = Bqkv + (size_t)(kC + r) * kKp; aSide = false; }
    else                { int r = rb - 3584; src = proj_w + (size_t)r * kC; dst = Bproj + (size_t)r * kKp;       aSide = false; }

    const int j0 = threadIdx.x * 4;
    float4 v = *(const float4*)&src[j0];
    float f[4] = {v.x, v.y, v.z, v.w};
    __nv_bfloat16 hi[4], lo[4];
#pragma unroll
    for (int t = 0; t < 4; t++) {
        hi[t] = __float2bfloat16(f[t]);
        lo[t] = __float2bfloat16(f[t] - __bfloat162float(hi[t]));
    }
    uint32_t hp0 = pack_bf2(hi[0], hi[1]), hp1 = pack_bf2(hi[2], hi[3]);
    uint32_t lp0 = pack_bf2(lo[0], lo[1]), lp1 = pack_bf2(lo[2], lo[3]);
    uint32_t* d0 = (uint32_t*)(dst + j0);
    uint32_t* d1 = (uint32_t*)(dst + kC + j0);
    uint32_t* d2 = (uint32_t*)(dst + 2 * kC + j0);
    d0[0] = hp0; d0[1] = hp1;
    if (aSide) { d1[0] = lp0; d1[1] = lp1; d2[0] = hp0; d2[1] = hp1; }
    else       { d1[0] = hp0; d1[1] = hp1; d2[0] = lp0; d2[1] = lp1; }
}

// ===================== templated mma.sync bf16 GEMM =====================
// MODE 0: C0/C1 fp32 split-column output (+bias)
// MODE 1: qkv epilogue -> qbf/kbf triples + yv3 triple ([bh][d][384])
// MODE 2: per-(b,h) qk: S = 0.125 * q@k^T
template<int KBYTES, int NITER, int MODE>
__global__ __launch_bounds__(256) void mma_gemm_t(
    const __nv_bfloat16* __restrict__ A,
    const __nv_bfloat16* __restrict__ Bw,
    float* __restrict__ C0, float* __restrict__ C1,
    const float* __restrict__ bias, int split, int ld0, int ld1,
    __nv_bfloat16* __restrict__ qbf, __nv_bfloat16* __restrict__ kbf,
    __nv_bfloat16* __restrict__ yv3)
{
    __shared__ __align__(16) char smem[2][16384];
    const int tid = threadIdx.x;
    const int wid = tid >> 5, lane = tid & 31;
    const int warp_m = wid >> 1, warp_n = wid & 1;

    int m0, n0;
    const char *Ag, *Bg;
    if (MODE == 2) {
        const size_t off = (size_t)blockIdx.x * 128 * KBYTES;
        Ag = (const char*)A + off;
        Bg = (const char*)Bw + off;
        m0 = 0; n0 = 0;
    } else {
        m0 = blockIdx.y * 128; n0 = blockIdx.x * 128;
        Ag = (const char*)A  + (size_t)m0 * KBYTES;
        Bg = (const char*)Bw + (size_t)n0 * KBYTES;
    }

    const int lr = tid >> 2, lc = tid & 3;
    const uint32_t lso  = (uint32_t)(lr * 64 + ((lc ^ (lr & 3)) << 4));
    const uint32_t lso2 = (uint32_t)((lr + 64) * 64 + ((lc ^ ((lr + 64) & 3)) << 4));
    uint32_t sbase = smem_u32(&smem[0][0]);

    auto stage_load = [&](int st, int k0b) {
        uint32_t sA = sbase + st * 16384;
        uint32_t sB = sA + 8192;
        const char* a0 = Ag + (size_t)lr * KBYTES + k0b + lc * 16;
        const char* b0 = Bg + (size_t)lr * KBYTES + k0b + lc * 16;
        cp_async16(sA + lso,  a0);
        cp_async16(sB + lso,  b0);
        cp_async16(sA + lso2, a0 + (size_t)64 * KBYTES);
        cp_async16(sB + lso2, b0 + (size_t)64 * KBYTES);
    };

    float acc[2][8][4];
#pragma unroll
    for (int i = 0; i < 2; i++)
#pragma unroll
        for (int j = 0; j < 8; j++)
#pragma unroll
            for (int t = 0; t < 4; t++) acc[i][j][t] = 0.f;

    stage_load(0, 0);
    cp_commit();

    const int a_row = warp_m * 32 + (lane & 15);
    const int a_chsel = lane >> 4;
    const int b_mi = lane >> 3;
    const int b_row = warp_n * 64 + ((b_mi >> 1) << 3) + (lane & 7);
    const int b_chsel = b_mi & 1;

    for (int it = 0; it < NITER; it++) {
        cp_wait0();
        __syncthreads();
        if (it + 1 < NITER) { stage_load((it + 1) & 1, (it + 1) * 64); cp_commit(); }

        const uint32_t sA = sbase + (it & 1) * 16384;
        const uint32_t sB = sA + 8192;
#pragma unroll
        for (int kk = 0; kk < 2; kk++) {
            uint32_t a[2][4];
#pragma unroll
            for (int i = 0; i < 2; i++) {
                int r = a_row + i * 16;
                int ch = 2 * kk + a_chsel;
                ldsm_x4(a[i], sA + r * 64 + ((ch ^ (r & 3)) << 4));
            }
            uint32_t b[8][2];
#pragma unroll
            for (int g = 0; g < 4; g++) {
                int r = b_row + g * 16;
                int ch = 2 * kk + b_chsel;
                uint32_t rr[4];
                ldsm_x4(rr, sB + r * 64 + ((ch ^ (r & 3)) << 4));
                b[2 * g][0] = rr[0]; b[2 * g][1] = rr[1];
                b[2 * g + 1][0] = rr[2]; b[2 * g + 1][1] = rr[3];
            }
#pragma unroll
            for (int i = 0; i < 2; i++)
#pragma unroll
                for (int j = 0; j < 8; j++)
                    mma16816(acc[i][j], a[i], b[j]);
        }
        __syncthreads();
    }

    const int gq = lane >> 2, t4 = lane & 3;

    if (MODE == 2) {
        float* Sp = C0 + (size_t)blockIdx.x * kN * kN;
#pragma unroll
        for (int i = 0; i < 2; i++) {
#pragma unroll
            for (int j = 0; j < 8; j++) {
                int col = warp_n * 64 + j * 8 + t4 * 2;
                int r0 = warp_m * 32 + i * 16 + gq;
                *(float2*)&Sp[(size_t)r0 * kN + col] =
                    make_float2(acc[i][j][0] * 0.125f, acc[i][j][1] * 0.125f);
                *(float2*)&Sp[(size_t)(r0 + 8) * kN + col] =
                    make_float2(acc[i][j][2] * 0.125f, acc[i][j][3] * 0.125f);
            }
        }
        return;
    }

    if (MODE == 1) {
        auto emit = [&](int row, int colg, float f0, float f1) {
            if (colg < 1024) {
                const bool isQ = colg < 512;
                const int c = isQ ? colg : colg - 512;
                const int h = c >> 6, d = c & 63;
                __nv_bfloat16 h0 = __float2bfloat16(f0);
                __nv_bfloat16 h1 = __float2bfloat16(f1);
                __nv_bfloat16 l0 = __float2bfloat16(f0 - __bfloat162float(h0));
                __nv_bfloat16 l1 = __float2bfloat16(f1 - __bfloat162float(h1));
                uint32_t hp = pack_bf2(h0, h1);
                uint32_t lp = pack_bf2(l0, l1);
                const int bb = row >> 7, nn = row & 127;
                __nv_bfloat16* base = (isQ ? qbf : kbf)
                    + ((size_t)((bb * kH + h) * kN + nn)) * kKq + d;
                *(uint32_t*)(base)       = hp;
                *(uint32_t*)(base + 64)  = isQ ? lp : hp;
                *(uint32_t*)(base + 128) = isQ ? hp : lp;
            } else {
                // yv -> yv3 triple (hi|hi|lo), layout [bh][d][384m], row=(b,m)
                const int c = colg - 1024;
                const int h = c >> 6, d = c & 63;
                const int bb = row >> 7, m = row & 127;
                __nv_bfloat16* b0 = yv3
                    + ((size_t)((bb * kH + h) * kHD + d)) * kKm + m;
                __nv_bfloat16 h0 = __float2bfloat16(f0);
                __nv_bfloat16 l0 = __float2bfloat16(f0 - __bfloat162float(h0));
                b0[0] = h0; b0[128] = h0; b0[256] = l0;
                __nv_bfloat16* b1 = b0 + kKm;  // d+1 row
                __nv_bfloat16 h1 = __float2bfloat16(f1);
                __nv_bfloat16 l1 = __float2bfloat16(f1 - __bfloat162float(h1));
                b1[0] = h1; b1[128] = h1; b1[256] = l1;
            }
        };
#pragma unroll
        for (int i = 0; i < 2; i++) {
#pragma unroll
            for (int j = 0; j < 8; j++) {
                int colg = n0 + warp_n * 64 + j * 8 + t4 * 2;
                int row0 = m0 + warp_m * 32 + i * 16 + gq;
                emit(row0,     colg, acc[i][j][0], acc[i][j][1]);
                emit(row0 + 8, colg, acc[i][j][2], acc[i][j][3]);
            }
        }
        return;
    }

    // MODE 0
#pragma unroll
    for (int i = 0; i < 2; i++) {
#pragma unroll
        for (int j = 0; j < 8; j++) {
            int colg = n0 + warp_n * 64 + j * 8 + t4 * 2;
            float bz0 = bias ? bias[colg]     : 0.f;
            float bz1 = bias ? bias[colg + 1] : 0.f;
            float* Cc; int ldc, cc;
            if (colg < split) { Cc = C0; ldc = ld0; cc = colg; }
            else              { Cc = C1; ldc = ld1; cc = colg - split; }
            int row0 = m0 + warp_m * 32 + i * 16 + gq;
            *(float2*)&Cc[(size_t)row0 * ldc + cc] =
                make_float2(acc[i][j][0] + bz0, acc[i][j][1] + bz1);
            *(float2*)&Cc[(size_t)(row0 + 8) * ldc + cc] =
                make_float2(acc[i][j][2] + bz0, acc[i][j][3] + bz1);
        }
    }
}

// ===================== fused att v2: split 4x along bh =====================
// Grid (4, 128): blockIdx.x = bh quarter (32 heads), blockIdx.y = n.
// 256 threads, ~40 KB dynamic smem.
__global__ __launch_bounds__(256) void fused_att_kernel(
    const float* __restrict__ S, const float* __restrict__ assign,
    const void* __restrict__ mask, const float* __restrict__ rel_bias,
    __nv_bfloat16* __restrict__ W3)
{
    extern __shared__ float sm[];
    float* Ss   = sm;                         // [32][132]
    float* AsT  = Ss + 32 * 132;              // [17][132]
    float* Atmp = AsT + 17 * 132 + 4;         // [2176]
    float* Ls   = Atmp + 2176;                // [32][20]
    float* Ps   = Ls + 32 * 20;               // [32][20]
    float* rb   = Ps + 32 * 20;               // [136]
    int*   mk   = (int*)(rb + 136);           // [17]
    const int t = threadIdx.x;
    const int q = blockIdx.x;                 // bh quarter
    const int n = blockIdx.y;
    const int bh0 = q * 32;

    // ---- loads ----
    const float* arow = assign + (size_t)n * (kN * kR);
    for (int i = t; i < 544; i += 256)
        *(float4*)&Atmp[i * 4] = *(const float4*)&arow[i * 4];
    if (t < 136) rb[t] = rel_bias[t];
    if (t < 17) {
        int mode = g_mask_mode;
        int idx = n * kR + t;
        bool m_;
        if (mode == 0)      m_ = ((const int*)mask)[idx] != 0;
        else if (mode == 1) m_ = ((const float*)mask)[idx] != 0.f;
        else                m_ = ((const unsigned char*)mask)[idx] != 0;
        mk[t] = m_ ? 1 : 0;
    }
    {
        // S slice: 32 rows x 128. thread: bh = t>>3, seg = t&7 (16 floats)
        const int bh = t >> 3, seg = t & 7;
        const float* srow = S + ((size_t)(bh0 + bh) * kN + n) * kN + seg * 16;
        float* drow = Ss + bh * 132 + seg * 16;
#pragma unroll
        for (int g = 0; g < 4; g++)
            *(float4*)&drow[g * 4] = *(const float4*)&srow[g * 4];
    }
    __syncthreads();
    for (int i = t; i < kN * kR; i += 256) {
        int m = i / kR, r = i - m * kR;
        AsT[r * 132 + m] = Atmp[i];
    }
    __syncthreads();

    // ---- logits: 544 outputs (32 bh x 17 r), strided over 256 threads ----
    for (int o = t; o < 32 * kR; o += 256) {
        const int bh = o / kR, r = o - bh * kR;
        const float* srow = Ss + bh * 132;
        const float* atr  = AsT + r * 132;
        float a0 = 0.f, a1 = 0.f, a2 = 0.f, a3 = 0.f;
#pragma unroll 8
        for (int mg = 0; mg < 32; mg++) {
            float4 s = *(const float4*)&srow[mg * 4];
            float4 a = *(const float4*)&atr[mg * 4];
            a0 += s.x * a.x; a1 += s.y * a.y;
            a2 += s.z * a.z; a3 += s.w * a.w;
        }
        const int h = (bh0 + bh) & 7;
        Ls[bh * 20 + r] = mk[r] ? neg_inf()
                                : ((a0 + a1) + (a2 + a3) + rb[h * kR + r]);
    }
    __syncthreads();

    // ---- softmax (32 threads, one bh each) ----
    if (t < 32) {
        float mx = neg_inf();
#pragma unroll
        for (int r = 0; r < kR; r++) mx = fmaxf(mx, Ls[t * 20 + r]);
        float s = 0.f;
#pragma unroll
        for (int r = 0; r < kR; r++) {
            float e = __expf(Ls[t * 20 + r] - mx);
            Ps[t * 20 + r] = e; s += e;
        }
        float inv = 1.f / s;
#pragma unroll
        for (int r = 0; r < kR; r++) Ps[t * 20 + r] *= inv;
    }
    __syncthreads();

    // ---- W[bh][m] = sum_r P[bh][r]*AsT[r][m]; emit hi|lo|hi triple ----
    {
        const int bh = t >> 3, mseg = t & 7;    // 16 m per thread
        float p[kR];
#pragma unroll
        for (int r = 0; r < kR; r++) p[r] = Ps[bh * 20 + r];
        __nv_bfloat16* wrow = W3 + ((size_t)(bh0 + bh) * kN + n) * kKm;
#pragma unroll
        for (int g = 0; g < 4; g++) {
            const int m = mseg * 16 + g * 4;
            float ax = 0.f, ay = 0.f, az = 0.f, aw = 0.f;
#pragma unroll
            for (int r = 0; r < kR; r++) {
                float4 a = *(const float4*)&AsT[r * 132 + m];
                ax += p[r] * a.x; ay += p[r] * a.y;
                az += p[r] * a.z; aw += p[r] * a.w;
            }
            __nv_bfloat16 h0 = __float2bfloat16(ax), h1 = __float2bfloat16(ay);
            __nv_bfloat16 h2 = __float2bfloat16(az), h3 = __float2bfloat16(aw);
            __nv_bfloat16 l0 = __float2bfloat16(ax - __bfloat162float(h0));
            __nv_bfloat16 l1 = __float2bfloat16(ay - __bfloat162float(h1));
            __nv_bfloat16 l2 = __float2bfloat16(az - __bfloat162float(h2));
            __nv_bfloat16 l3 = __float2bfloat16(aw - __bfloat162float(h3));
            uint32_t* o0 = (uint32_t*)(wrow + m);
            uint32_t* o1 = (uint32_t*)(wrow + 128 + m);
            uint32_t* o2 = (uint32_t*)(wrow + 256 + m);
            o0[0] = pack_bf2(h0, h1); o0[1] = pack_bf2(h2, h3);
            o1[0] = pack_bf2(l0, l1); o1[1] = pack_bf2(l2, l3);
            o2[0] = pack_bf2(h0, h1); o2[1] = pack_bf2(h2, h3);
        }
    }
}

// ===================== av mma: O[n][d] = W3 @ yv3^T per (b,h) ===============
__global__ __launch_bounds__(256) void av_mma_kernel(
    const __nv_bfloat16* __restrict__ W3, const __nv_bfloat16* __restrict__ yv3,
    __nv_bfloat16* __restrict__ AO)
{
    __shared__ __align__(16) char smem[2][12288];
    const int tid = threadIdx.x, wid = tid >> 5, lane = tid & 31;
    const int bh = blockIdx.x;
    const int warp_m = wid >> 1, warp_n = wid & 1;
    const char* Ag = (const char*)W3  + (size_t)bh * kN  * (kKm * 2);
    const char* Bg = (const char*)yv3 + (size_t)bh * kHD * (kKm * 2);
    const int lr = tid >> 2, lc = tid & 3;
    const uint32_t lso  = (uint32_t)(lr * 64 + ((lc ^ (lr & 3)) << 4));
    const uint32_t lso2 = (uint32_t)((lr + 64) * 64 + ((lc ^ ((lr + 64) & 3)) << 4));
    uint32_t sbase = smem_u32(&smem[0][0]);

    auto stage_load = [&](int st, int k0b) {
        uint32_t sA = sbase + st * 12288;
        uint32_t sB = sA + 8192;
        const char* a0 = Ag + (size_t)lr * 768 + k0b + lc * 16;
        cp_async16(sA + lso,  a0);
        cp_async16(sA + lso2, a0 + (size_t)64 * 768);
        cp_async16(sB + lso,  Bg + (size_t)lr * 768 + k0b + lc * 16);
    };

    float acc[2][4][4];
#pragma unroll
    for (int i = 0; i < 2; i++)
#pragma unroll
        for (int j = 0; j < 4; j++)
#pragma unroll
            for (int t = 0; t < 4; t++) acc[i][j][t] = 0.f;

    stage_load(0, 0);
    cp_commit();

    const int a_row = warp_m * 32 + (lane & 15);
    const int a_chsel = lane >> 4;
    const int b_mi = lane >> 3;
    const int b_row = warp_n * 32 + ((b_mi >> 1) << 3) + (lane & 7);
    const int b_chsel = b_mi & 1;

    for (int it = 0; it < 12; it++) {
        cp_wait0();
        __syncthreads();
        if (it + 1 < 12) { stage_load((it + 1) & 1, (it + 1) * 64); cp_commit(); }

        const uint32_t sA = sbase + (it & 1) * 12288;
        const uint32_t sB = sA + 8192;
#pragma unroll
        for (int kk = 0; kk < 2; kk++) {
            uint32_t a[2][4];
#pragma unroll
            for (int i = 0; i < 2; i++) {
                int r = a_row + i * 16;
                int ch = 2 * kk + a_chsel;
                ldsm_x4(a[i], sA + r * 64 + ((ch ^ (r & 3)) << 4));
            }
            uint32_t b[4][2];
#pragma unroll
            for (int g = 0; g < 2; g++) {
                int r = b_row + g * 16;
                int ch = 2 * kk + b_chsel;
                uint32_t rr[4];
                ldsm_x4(rr, sB + r * 64 + ((ch ^ (r & 3)) << 4));
                b[2 * g][0] = rr[0]; b[2 * g][1] = rr[1];
                b[2 * g + 1][0] = rr[2]; b[2 * g + 1][1] = rr[3];
            }
#pragma unroll
            for (int i = 0; i < 2; i++)
#pragma unroll
                for (int j = 0; j < 4; j++)
                    mma16816(acc[i][j], a[i], b[j]);
        }
        __syncthreads();
    }

    const int gq = lane >> 2, t4 = lane & 3;
    const int b_ = bh >> 3, h_ = bh & 7;
#pragma unroll
    for (int i = 0; i < 2; i++) {
#pragma unroll
        for (int j = 0; j < 4; j++) {
            const int d = warp_n * 32 + j * 8 + t4 * 2;
            const int c = h_ * kHD + d;
#pragma unroll
            for (int rr = 0; rr < 2; rr++) {
                const int nrow = warp_m * 32 + i * 16 + gq + rr * 8;
                const float f0 = acc[i][j][rr * 2], f1 = acc[i][j][rr * 2 + 1];
                __nv_bfloat16 h0 = __float2bfloat16(f0), h1 = __float2bfloat16(f1);
                __nv_bfloat16 l0 = __float2bfloat16(f0 - __bfloat162float(h0));
                __nv_bfloat16 l1 = __float2bfloat16(f1 - __bfloat162float(h1));
                __nv_bfloat16* base = AO + (size_t)(b_ * kN + nrow) * kKp + c;
                *(uint32_t*)(base)        = pack_bf2(h0, h1);
                *(uint32_t*)(base + 512)  = pack_bf2(l0, l1);
                *(uint32_t*)(base + 1024) = pack_bf2(h0, h1);
            }
        }
    }
}

// ===================== launch =====================
extern "C" void kernel_launch(void* const* d_in, const int* in_sizes, int n_in,
                              void* d_out, int out_size)
{
    const float* x        = (const float*)d_in[0];
    const float* assign   = (const float*)d_in[1];
    const void*  mask     = d_in[2];
    const float* q_w      = (const float*)d_in[3];
    const float* kv_w     = (const float*)d_in[4];
    const float* rel_bias = (const float*)d_in[5];
    const float* proj_w   = (const float*)d_in[6];
    const float* proj_b   = (const float*)d_in[7];

    float *S;
    __nv_bfloat16 *Ax, *Bqkv, *Bproj, *AO, *qbf, *kbf, *W3, *yv3;
    cudaGetSymbolAddress((void**)&S,   g_S);
    cudaGetSymbolAddress((void**)&Ax,    g_Ax);
    cudaGetSymbolAddress((void**)&Bqkv,  g_Bqkv);
    cudaGetSymbolAddress((void**)&Bproj, g_Bproj);
    cudaGetSymbolAddress((void**)&AO,    g_AO);
    cudaGetSymbolAddress((void**)&qbf,   g_qbf);
    cudaGetSymbolAddress((void**)&kbf,   g_kbf);
    cudaGetSymbolAddress((void**)&W3,    g_W3);
    cudaGetSymbolAddress((void**)&yv3,   g_yv3);

    const int ATT_SMEM = (32 * 132 + 17 * 132 + 4 + 2176 + 32 * 20 * 2 + 136 + 24) * 4;
    cudaFuncSetAttribute(fused_att_kernel,
                         cudaFuncAttributeMaxDynamicSharedMemorySize, ATT_SMEM);

    // 1. input hi/lo splits + mask probe
    convert_all_kernel<<<4097, 128>>>(x, q_w, kv_w, proj_w, mask, Ax, Bqkv, Bproj);

    // 2. fused q/kv projection -> qbf/kbf triples + yv3 triple
    mma_gemm_t<3072, 48, 1><<<dim3(12, 16), 256>>>(
        Ax, Bqkv, nullptr, nullptr, nullptr, 0, 0, 0, qbf, kbf, yv3);

    // 3. S = 0.125 * q@k^T per (b,h)
    mma_gemm_t<384, 6, 2><<<dim3(128, 1), 256>>>(
        qbf, kbf, S, nullptr, nullptr, 0, 0, 0, nullptr, nullptr, nullptr);

    // 4. fused logits + softmax + W (emits W3 triple), 4x bh-split
    fused_att_kernel<<<dim3(4, 128), 256, ATT_SMEM>>>(S, assign, mask, rel_bias, W3);

    // 5. O = W @ yv per (b,h) on tensor cores (emits AO triple)
    av_mma_kernel<<<128, 256>>>(W3, yv3, AO);

    // 6. out-proj: AO @ Bproj^T + bias
    mma_gemm_t<3072, 48, 0><<<dim3(4, 16), 256>>>(
        AO, Bproj, (float*)d_out, (float*)d_out, proj_b, 1 << 30, kC, kC,
        nullptr, nullptr, nullptr);
}

// round 8
// speedup vs baseline: 1.1091x; 1.1091x over previous
#include <cuda_runtime.h>
#include <cuda_bf16.h>
#include <cstdint>

// Problem dims
constexpr int kB  = 16;
constexpr int kN  = 128;
constexpr int kC  = 512;
constexpr int kH  = 8;
constexpr int kR  = 17;
constexpr int kHD = 64;
constexpr int kBN = kB * kN;    // 2048
constexpr int kKp = 3 * kC;     // 1536 split-K' (c contraction)
constexpr int kKq = 3 * kHD;    // 192 split-K' (d contraction, qk)

// Scratch (device globals; no allocations allowed)
__device__ float g_S[kB * kH * kN * kN];  // 8 MB (pre-scaled by 0.125)
__device__ float g_Wf[kB * kH * kN * kN]; // 8 MB attention weights fp32
__device__ float g_yvf[kB * kH * kN * kHD]; // 4 MB yv fp32 [bh][m][64]
__device__ int   g_mask_mode;
__device__ __nv_bfloat16 g_Ax[kBN * kKp];        // x hi|lo|hi
__device__ __nv_bfloat16 g_Bqkv[kKp * kKp];      // [q_w;kv_w] hi|hi|lo
__device__ __nv_bfloat16 g_Bproj[kC * kKp];      // proj_w hi|hi|lo
__device__ __nv_bfloat16 g_AO[kBN * kKp];        // O hi|lo|hi (av epilogue)
__device__ __nv_bfloat16 g_qbf[kB * kH * kN * kKq]; // q hi|lo|hi per (b,h)
__device__ __nv_bfloat16 g_kbf[kB * kH * kN * kKq]; // k hi|hi|lo per (b,h)

__device__ __forceinline__ float neg_inf() { return __int_as_float(0xFF800000); }

// ===================== baseline-PTX helpers =====================
__device__ __forceinline__ uint32_t smem_u32(const void* p) {
    uint32_t a;
    asm("{ .reg .u64 t; cvta.to.shared.u64 t, %1; cvt.u32.u64 %0, t; }"
        : "=r"(a) : "l"(p));
    return a;
}
__device__ __forceinline__ void cp_async16(uint32_t saddr, const void* gaddr) {
    asm volatile("cp.async.cg.shared.global [%0], [%1], 16;"
                 :: "r"(saddr), "l"(gaddr) : "memory");
}
__device__ __forceinline__ void cp_commit() {
    asm volatile("cp.async.commit_group;" ::: "memory");
}
__device__ __forceinline__ void cp_wait0() {
    asm volatile("cp.async.wait_group 0;" ::: "memory");
}
__device__ __forceinline__ void ldsm_x4(uint32_t* r, uint32_t addr) {
    asm volatile("ldmatrix.sync.aligned.m8n8.x4.shared.b16 {%0,%1,%2,%3}, [%4];"
                 : "=r"(r[0]), "=r"(r[1]), "=r"(r[2]), "=r"(r[3]) : "r"(addr));
}
__device__ __forceinline__ void mma16816(float* d, const uint32_t* a, const uint32_t* b) {
    asm volatile("mma.sync.aligned.m16n8k16.row.col.f32.bf16.bf16.f32 "
                 "{%0,%1,%2,%3}, {%4,%5,%6,%7}, {%8,%9}, {%0,%1,%2,%3};"
                 : "+f"(d[0]), "+f"(d[1]), "+f"(d[2]), "+f"(d[3])
                 : "r"(a[0]), "r"(a[1]), "r"(a[2]), "r"(a[3]),
                   "r"(b[0]), "r"(b[1]));
}
__device__ __forceinline__ uint32_t pack_bf2(__nv_bfloat16 lo, __nv_bfloat16 hi) {
    return ((uint32_t)__bfloat16_as_ushort(hi) << 16) | __bfloat16_as_ushort(lo);
}
__device__ __forceinline__ void sts32(uint32_t addr, uint32_t v) {
    asm volatile("st.shared.b32 [%0], %1;" :: "r"(addr), "r"(v) : "memory");
}
__device__ __forceinline__ void sts64(uint32_t addr, uint32_t v0, uint32_t v1) {
    asm volatile("st.shared.v2.b32 [%0], {%1,%2};" :: "r"(addr), "r"(v0), "r"(v1) : "memory");
}

// ===================== fused converts + mask probe =====================
__global__ __launch_bounds__(128) void convert_all_kernel(
    const float* __restrict__ x, const float* __restrict__ q_w,
    const float* __restrict__ kv_w, const float* __restrict__ proj_w,
    const void* __restrict__ mask,
    __nv_bfloat16* __restrict__ Ax, __nv_bfloat16* __restrict__ Bqkv,
    __nv_bfloat16* __restrict__ Bproj)
{
    const int rb = blockIdx.x;
    if (rb == 4096) {
        __shared__ int s_not_i32, s_not_f32;
        if (threadIdx.x == 0) { s_not_i32 = 0; s_not_f32 = 0; }
        __syncthreads();
        const unsigned int* w = (const unsigned int*)mask;
        int bad_i = 0, bad_f = 0;
        for (int i = threadIdx.x; i < 544; i += 128) {
            unsigned int v = w[i];
            if (v > 1u) bad_i = 1;
            if (v != 0u && v != 0x3F800000u) bad_f = 1;
        }
        if (bad_i) atomicOr(&s_not_i32, 1);
        if (bad_f) atomicOr(&s_not_f32, 1);
        __syncthreads();
        if (threadIdx.x == 0)
            g_mask_mode = (!s_not_i32) ? 0 : ((!s_not_f32) ? 1 : 2);
        return;
    }
    const float* src;
    __nv_bfloat16* dst;
    bool aSide;
    if (rb < 2048)      { src = x + (size_t)rb * kC;             dst = Ax + (size_t)rb * kKp;           aSide = true;  }
    else if (rb < 2560) { int r = rb - 2048; src = q_w + (size_t)r * kC;    dst = Bqkv + (size_t)r * kKp;        aSide = false; }
    else if (rb < 3584) { int r = rb - 2560; src = kv_w + (size_t)r * kC;   dst = Bqkv + (size_t)(kC + r) * kKp; aSide = false; }
    else                { int r = rb - 3584; src = proj_w + (size_t)r * kC; dst = Bproj + (size_t)r * kKp;       aSide = false; }

    const int j0 = threadIdx.x * 4;
    float4 v = *(const float4*)&src[j0];
    float f[4] = {v.x, v.y, v.z, v.w};
    __nv_bfloat16 hi[4], lo[4];
#pragma unroll
    for (int t = 0; t < 4; t++) {
        hi[t] = __float2bfloat16(f[t]);
        lo[t] = __float2bfloat16(f[t] - __bfloat162float(hi[t]));
    }
    uint32_t hp0 = pack_bf2(hi[0], hi[1]), hp1 = pack_bf2(hi[2], hi[3]);
    uint32_t lp0 = pack_bf2(lo[0], lo[1]), lp1 = pack_bf2(lo[2], lo[3]);
    uint32_t* d0 = (uint32_t*)(dst + j0);
    uint32_t* d1 = (uint32_t*)(dst + kC + j0);
    uint32_t* d2 = (uint32_t*)(dst + 2 * kC + j0);
    d0[0] = hp0; d0[1] = hp1;
    if (aSide) { d1[0] = lp0; d1[1] = lp1; d2[0] = hp0; d2[1] = hp1; }
    else       { d1[0] = hp0; d1[1] = hp1; d2[0] = lp0; d2[1] = lp1; }
}

// ===================== templated mma.sync bf16 GEMM =====================
// MODE 0: C0/C1 fp32 split-column output (+bias)
// MODE 1: qkv epilogue -> qbf/kbf triples + yvf fp32 [bh][m][64] (C1 = yvf)
// MODE 2: per-(b,h) qk: S = 0.125 * q@k^T
template<int KBYTES, int NITER, int MODE>
__global__ __launch_bounds__(256) void mma_gemm_t(
    const __nv_bfloat16* __restrict__ A,
    const __nv_bfloat16* __restrict__ Bw,
    float* __restrict__ C0, float* __restrict__ C1,
    const float* __restrict__ bias, int split, int ld0, int ld1,
    __nv_bfloat16* __restrict__ qbf, __nv_bfloat16* __restrict__ kbf)
{
    __shared__ __align__(16) char smem[2][16384];
    const int tid = threadIdx.x;
    const int wid = tid >> 5, lane = tid & 31;
    const int warp_m = wid >> 1, warp_n = wid & 1;

    int m0, n0;
    const char *Ag, *Bg;
    if (MODE == 2) {
        const size_t off = (size_t)blockIdx.x * 128 * KBYTES;
        Ag = (const char*)A + off;
        Bg = (const char*)Bw + off;
        m0 = 0; n0 = 0;
    } else {
        m0 = blockIdx.y * 128; n0 = blockIdx.x * 128;
        Ag = (const char*)A  + (size_t)m0 * KBYTES;
        Bg = (const char*)Bw + (size_t)n0 * KBYTES;
    }

    const int lr = tid >> 2, lc = tid & 3;
    const uint32_t lso  = (uint32_t)(lr * 64 + ((lc ^ (lr & 3)) << 4));
    const uint32_t lso2 = (uint32_t)((lr + 64) * 64 + ((lc ^ ((lr + 64) & 3)) << 4));
    uint32_t sbase = smem_u32(&smem[0][0]);

    auto stage_load = [&](int st, int k0b) {
        uint32_t sA = sbase + st * 16384;
        uint32_t sB = sA + 8192;
        const char* a0 = Ag + (size_t)lr * KBYTES + k0b + lc * 16;
        const char* b0 = Bg + (size_t)lr * KBYTES + k0b + lc * 16;
        cp_async16(sA + lso,  a0);
        cp_async16(sB + lso,  b0);
        cp_async16(sA + lso2, a0 + (size_t)64 * KBYTES);
        cp_async16(sB + lso2, b0 + (size_t)64 * KBYTES);
    };

    float acc[2][8][4];
#pragma unroll
    for (int i = 0; i < 2; i++)
#pragma unroll
        for (int j = 0; j < 8; j++)
#pragma unroll
            for (int t = 0; t < 4; t++) acc[i][j][t] = 0.f;

    stage_load(0, 0);
    cp_commit();

    const int a_row = warp_m * 32 + (lane & 15);
    const int a_chsel = lane >> 4;
    const int b_mi = lane >> 3;
    const int b_row = warp_n * 64 + ((b_mi >> 1) << 3) + (lane & 7);
    const int b_chsel = b_mi & 1;

    for (int it = 0; it < NITER; it++) {
        cp_wait0();
        __syncthreads();
        if (it + 1 < NITER) { stage_load((it + 1) & 1, (it + 1) * 64); cp_commit(); }

        const uint32_t sA = sbase + (it & 1) * 16384;
        const uint32_t sB = sA + 8192;
#pragma unroll
        for (int kk = 0; kk < 2; kk++) {
            uint32_t a[2][4];
#pragma unroll
            for (int i = 0; i < 2; i++) {
                int r = a_row + i * 16;
                int ch = 2 * kk + a_chsel;
                ldsm_x4(a[i], sA + r * 64 + ((ch ^ (r & 3)) << 4));
            }
            uint32_t b[8][2];
#pragma unroll
            for (int g = 0; g < 4; g++) {
                int r = b_row + g * 16;
                int ch = 2 * kk + b_chsel;
                uint32_t rr[4];
                ldsm_x4(rr, sB + r * 64 + ((ch ^ (r & 3)) << 4));
                b[2 * g][0] = rr[0]; b[2 * g][1] = rr[1];
                b[2 * g + 1][0] = rr[2]; b[2 * g + 1][1] = rr[3];
            }
#pragma unroll
            for (int i = 0; i < 2; i++)
#pragma unroll
                for (int j = 0; j < 8; j++)
                    mma16816(acc[i][j], a[i], b[j]);
        }
        __syncthreads();
    }

    const int gq = lane >> 2, t4 = lane & 3;

    if (MODE == 2) {
        float* Sp = C0 + (size_t)blockIdx.x * kN * kN;
#pragma unroll
        for (int i = 0; i < 2; i++) {
#pragma unroll
            for (int j = 0; j < 8; j++) {
                int col = warp_n * 64 + j * 8 + t4 * 2;
                int r0 = warp_m * 32 + i * 16 + gq;
                *(float2*)&Sp[(size_t)r0 * kN + col] =
                    make_float2(acc[i][j][0] * 0.125f, acc[i][j][1] * 0.125f);
                *(float2*)&Sp[(size_t)(r0 + 8) * kN + col] =
                    make_float2(acc[i][j][2] * 0.125f, acc[i][j][3] * 0.125f);
            }
        }
        return;
    }

    if (MODE == 1) {
        auto emit = [&](int row, int colg, float f0, float f1) {
            if (colg < 1024) {
                const bool isQ = colg < 512;
                const int c = isQ ? colg : colg - 512;
                const int h = c >> 6, d = c & 63;
                __nv_bfloat16 h0 = __float2bfloat16(f0);
                __nv_bfloat16 h1 = __float2bfloat16(f1);
                __nv_bfloat16 l0 = __float2bfloat16(f0 - __bfloat162float(h0));
                __nv_bfloat16 l1 = __float2bfloat16(f1 - __bfloat162float(h1));
                uint32_t hp = pack_bf2(h0, h1);
                uint32_t lp = pack_bf2(l0, l1);
                const int bb = row >> 7, nn = row & 127;
                __nv_bfloat16* base = (isQ ? qbf : kbf)
                    + ((size_t)((bb * kH + h) * kN + nn)) * kKq + d;
                *(uint32_t*)(base)       = hp;
                *(uint32_t*)(base + 64)  = isQ ? lp : hp;
                *(uint32_t*)(base + 128) = isQ ? hp : lp;
            } else {
                // yv -> compact fp32 [bh][m][64]
                const int c = colg - 1024;
                const int h = c >> 6, d = c & 63;
                const int bb = row >> 7, m = row & 127;
                *(float2*)&C1[((size_t)((bb * kH + h) * kN + m)) * kHD + d] =
                    make_float2(f0, f1);
            }
        };
#pragma unroll
        for (int i = 0; i < 2; i++) {
#pragma unroll
            for (int j = 0; j < 8; j++) {
                int colg = n0 + warp_n * 64 + j * 8 + t4 * 2;
                int row0 = m0 + warp_m * 32 + i * 16 + gq;
                emit(row0,     colg, acc[i][j][0], acc[i][j][1]);
                emit(row0 + 8, colg, acc[i][j][2], acc[i][j][3]);
            }
        }
        return;
    }

    // MODE 0
#pragma unroll
    for (int i = 0; i < 2; i++) {
#pragma unroll
        for (int j = 0; j < 8; j++) {
            int colg = n0 + warp_n * 64 + j * 8 + t4 * 2;
            float bz0 = bias ? bias[colg]     : 0.f;
            float bz1 = bias ? bias[colg + 1] : 0.f;
            float* Cc; int ldc, cc;
            if (colg < split) { Cc = C0; ldc = ld0; cc = colg; }
            else              { Cc = C1; ldc = ld1; cc = colg - split; }
            int row0 = m0 + warp_m * 32 + i * 16 + gq;
            *(float2*)&Cc[(size_t)row0 * ldc + cc] =
                make_float2(acc[i][j][0] + bz0, acc[i][j][1] + bz1);
            *(float2*)&Cc[(size_t)(row0 + 8) * ldc + cc] =
                make_float2(acc[i][j][2] + bz0, acc[i][j][3] + bz1);
        }
    }
}

// ===================== att v3: block per (b,n), register-blocked ============
__global__ __launch_bounds__(256) void att_kernel(
    const float* __restrict__ S, const float* __restrict__ assign,
    const void* __restrict__ mask, const float* __restrict__ rel_bias,
    float* __restrict__ Wf)
{
    __shared__ float Atmp[2176];
    __shared__ float AsT[kR * 132];
    __shared__ float Ss[kH * 132];
    __shared__ float Lp[272];
    __shared__ float Ls[kH * 20];
    __shared__ float Ps[kH * 20];
    __shared__ float rb[136];
    __shared__ int   mk[kR];

    const int t = threadIdx.x;
    const int b = blockIdx.x >> 7, n = blockIdx.x & 127;

    const float* arow = assign + (size_t)n * (kN * kR);
    for (int i = t; i < 544; i += 256)
        *(float4*)&Atmp[i * 4] = *(const float4*)&arow[i * 4];
    if (t < 136) rb[t] = rel_bias[t];
    if (t < kR) {
        int mode = g_mask_mode;
        int idx = n * kR + t;
        bool m_;
        if (mode == 0)      m_ = ((const int*)mask)[idx] != 0;
        else if (mode == 1) m_ = ((const float*)mask)[idx] != 0.f;
        else                m_ = ((const unsigned char*)mask)[idx] != 0;
        mk[t] = m_ ? 1 : 0;
    }
    {
        const int h = t >> 5, m0 = (t & 31) * 4;
        *(float4*)&Ss[h * 132 + m0] =
            *(const float4*)&S[(((size_t)(b * kH + h)) * kN + n) * kN + m0];
    }
    __syncthreads();
    for (int i = t; i < kN * kR; i += 256) {
        int m = i / kR, r = i - m * kR;
        AsT[r * 132 + m] = Atmp[i];
    }
    __syncthreads();

    // logits: 272 half-dots (h,r,half of m)
    for (int o = t; o < 272; o += 256) {
        const int hr = o >> 1, half = o & 1;
        const int h = hr / kR, r = hr - h * kR;
        const float* s = Ss + h * 132 + half * 64;
        const float* a = AsT + r * 132 + half * 64;
        float a0 = 0.f, a1 = 0.f, a2 = 0.f, a3 = 0.f;
#pragma unroll
        for (int mg = 0; mg < 16; mg++) {
            float4 sv = *(const float4*)&s[mg * 4];
            float4 av = *(const float4*)&a[mg * 4];
            a0 += sv.x * av.x; a1 += sv.y * av.y;
            a2 += sv.z * av.z; a3 += sv.w * av.w;
        }
        Lp[o] = (a0 + a1) + (a2 + a3);
    }
    __syncthreads();
    if (t < 136) {
        const int h = t / kR, r = t - h * kR;
        float v = Lp[2 * t] + Lp[2 * t + 1];
        Ls[h * 20 + r] = mk[r] ? neg_inf() : (v + rb[t]);
    }
    __syncthreads();

    if (t < kH) {
        float mx = neg_inf();
#pragma unroll
        for (int r = 0; r < kR; r++) mx = fmaxf(mx, Ls[t * 20 + r]);
        float s = 0.f;
#pragma unroll
        for (int r = 0; r < kR; r++) {
            float e = __expf(Ls[t * 20 + r] - mx);
            Ps[t * 20 + r] = e; s += e;
        }
        float inv = 1.f / s;
#pragma unroll
        for (int r = 0; r < kR; r++) Ps[t * 20 + r] *= inv;
    }
    __syncthreads();

    // W phase: thread = m column, all 8 h (A read once per (r,m))
    if (t < kN) {
        float acc[kH];
#pragma unroll
        for (int h = 0; h < kH; h++) acc[h] = 0.f;
#pragma unroll
        for (int r = 0; r < kR; r++) {
            float a = AsT[r * 132 + t];
#pragma unroll
            for (int h = 0; h < kH; h++) acc[h] += Ps[h * 20 + r] * a;
        }
#pragma unroll
        for (int h = 0; h < kH; h++)
            Wf[(((size_t)(b * kH + h)) * kN + n) * kN + t] = acc[h];
    }
}

// ===================== av combo mma: O = W @ yv^T per (b,h) =================
// Loads W fp32 [bh][n][128] and yv fp32 [bh][m][64]; converts to hi/lo SMEM
// tiles; 12-stage combo schedule == hi/lo split-K. Emits AO triple.
__global__ __launch_bounds__(256) void av_mma_kernel(
    const float* __restrict__ Wf, const float* __restrict__ yvf,
    __nv_bfloat16* __restrict__ AO)
{
    extern __shared__ __align__(16) char dsm[];
    const int tid = threadIdx.x, wid = tid >> 5, lane = tid & 31;
    const int bh = blockIdx.x;
    const int warp_m = wid >> 1, warp_n = wid & 1;
    const uint32_t sbase = smem_u32(dsm);           // A stages: 8 x 8KB
    const uint32_t vbase = sbase + 65536u;          // B stages: 8 x 4KB

    // ---- load W -> A hi/lo stages ----
    const float* Wb = Wf + (size_t)bh * kN * kN;
    {
        const int mq = tid & 31, r0 = tid >> 5;     // m-quad, row base
#pragma unroll
        for (int i = 0; i < 16; i++) {
            const int row = r0 + 8 * i;
            float4 v = *(const float4*)&Wb[(size_t)row * kN + mq * 4];
            float f[4] = {v.x, v.y, v.z, v.w};
            __nv_bfloat16 hi[4], lo[4];
#pragma unroll
            for (int u = 0; u < 4; u++) {
                hi[u] = __float2bfloat16(f[u]);
                lo[u] = __float2bfloat16(f[u] - __bfloat162float(hi[u]));
            }
            const int m0 = mq * 4;
            const int stage = m0 >> 5;
            const int ch = (m0 & 31) >> 3;
            const int hb = (m0 & 7) >> 2;
            uint32_t addr = sbase + stage * 8192 + row * 64
                          + ((ch ^ (row & 3)) << 4) + hb * 8;
            sts64(addr, pack_bf2(hi[0], hi[1]), pack_bf2(hi[2], hi[3]));
            sts64(addr + 4 * 8192, pack_bf2(lo[0], lo[1]), pack_bf2(lo[2], lo[3]));
        }
    }
    // ---- load yv -> B hi/lo stages (transpose [m][d] -> [d][m]) ----
    const float* Vb = yvf + (size_t)bh * kN * kHD;
    {
        const int dq = tid & 15, mp0 = tid >> 4;    // d-quad, m-pair base
#pragma unroll
        for (int i = 0; i < 4; i++) {
            const int mp = mp0 + 16 * i;            // m = 2*mp
            const int m0 = 2 * mp;
            float4 v0 = *(const float4*)&Vb[(size_t)m0 * kHD + dq * 4];
            float4 v1 = *(const float4*)&Vb[(size_t)(m0 + 1) * kHD + dq * 4];
            float f0[4] = {v0.x, v0.y, v0.z, v0.w};
            float f1[4] = {v1.x, v1.y, v1.z, v1.w};
            const int stage = m0 >> 5;
            const int ch = (m0 & 31) >> 3;
            const int ob = (m0 & 7) * 2;
#pragma unroll
            for (int u = 0; u < 4; u++) {
                const int row = dq * 4 + u;
                __nv_bfloat16 h0 = __float2bfloat16(f0[u]);
                __nv_bfloat16 h1 = __float2bfloat16(f1[u]);
                __nv_bfloat16 l0 = __float2bfloat16(f0[u] - __bfloat162float(h0));
                __nv_bfloat16 l1 = __float2bfloat16(f1[u] - __bfloat162float(h1));
                uint32_t addr = vbase + stage * 4096 + row * 64
                              + ((ch ^ (row & 3)) << 4) + ob;
                sts32(addr, pack_bf2(h0, h1));
                sts32(addr + 4 * 4096, pack_bf2(l0, l1));
            }
        }
    }
    __syncthreads();

    float acc[2][4][4];
#pragma unroll
    for (int i = 0; i < 2; i++)
#pragma unroll
        for (int j = 0; j < 4; j++)
#pragma unroll
            for (int t = 0; t < 4; t++) acc[i][j][t] = 0.f;

    const int a_row = warp_m * 32 + (lane & 15);
    const int a_chsel = lane >> 4;
    const int b_mi = lane >> 3;
    const int b_row = warp_n * 32 + ((b_mi >> 1) << 3) + (lane & 7);
    const int b_chsel = b_mi & 1;

    const int schedA[12] = {0,1,2,3, 4,5,6,7, 0,1,2,3};
    const int schedB[12] = {0,1,2,3, 0,1,2,3, 4,5,6,7};

#pragma unroll
    for (int it = 0; it < 12; it++) {
        const uint32_t sA = sbase + schedA[it] * 8192;
        const uint32_t sB = vbase + schedB[it] * 4096;
#pragma unroll
        for (int kk = 0; kk < 2; kk++) {
            uint32_t a[2][4];
#pragma unroll
            for (int i = 0; i < 2; i++) {
                int r = a_row + i * 16;
                int ch = 2 * kk + a_chsel;
                ldsm_x4(a[i], sA + r * 64 + ((ch ^ (r & 3)) << 4));
            }
            uint32_t b[4][2];
#pragma unroll
            for (int g = 0; g < 2; g++) {
                int r = b_row + g * 16;
                int ch = 2 * kk + b_chsel;
                uint32_t rr[4];
                ldsm_x4(rr, sB + r * 64 + ((ch ^ (r & 3)) << 4));
                b[2 * g][0] = rr[0]; b[2 * g][1] = rr[1];
                b[2 * g + 1][0] = rr[2]; b[2 * g + 1][1] = rr[3];
            }
#pragma unroll
            for (int i = 0; i < 2; i++)
#pragma unroll
                for (int j = 0; j < 4; j++)
                    mma16816(acc[i][j], a[i], b[j]);
        }
    }

    const int gq = lane >> 2, t4 = lane & 3;
    const int b_ = bh >> 3, h_ = bh & 7;
#pragma unroll
    for (int i = 0; i < 2; i++) {
#pragma unroll
        for (int j = 0; j < 4; j++) {
            const int d = warp_n * 32 + j * 8 + t4 * 2;
            const int c = h_ * kHD + d;
#pragma unroll
            for (int rr = 0; rr < 2; rr++) {
                const int nrow = warp_m * 32 + i * 16 + gq + rr * 8;
                const float f0 = acc[i][j][rr * 2], f1 = acc[i][j][rr * 2 + 1];
                __nv_bfloat16 h0 = __float2bfloat16(f0), h1 = __float2bfloat16(f1);
                __nv_bfloat16 l0 = __float2bfloat16(f0 - __bfloat162float(h0));
                __nv_bfloat16 l1 = __float2bfloat16(f1 - __bfloat162float(h1));
                __nv_bfloat16* base = AO + (size_t)(b_ * kN + nrow) * kKp + c;
                *(uint32_t*)(base)        = pack_bf2(h0, h1);
                *(uint32_t*)(base + 512)  = pack_bf2(l0, l1);
                *(uint32_t*)(base + 1024) = pack_bf2(h0, h1);
            }
        }
    }
}

// ===================== launch =====================
extern "C" void kernel_launch(void* const* d_in, const int* in_sizes, int n_in,
                              void* d_out, int out_size)
{
    const float* x        = (const float*)d_in[0];
    const float* assign   = (const float*)d_in[1];
    const void*  mask     = d_in[2];
    const float* q_w      = (const float*)d_in[3];
    const float* kv_w     = (const float*)d_in[4];
    const float* rel_bias = (const float*)d_in[5];
    const float* proj_w   = (const float*)d_in[6];
    const float* proj_b   = (const float*)d_in[7];

    float *S, *Wfp, *yvf;
    __nv_bfloat16 *Ax, *Bqkv, *Bproj, *AO, *qbf, *kbf;
    cudaGetSymbolAddress((void**)&S,    g_S);
    cudaGetSymbolAddress((void**)&Wfp,  g_Wf);
    cudaGetSymbolAddress((void**)&yvf,  g_yvf);
    cudaGetSymbolAddress((void**)&Ax,    g_Ax);
    cudaGetSymbolAddress((void**)&Bqkv,  g_Bqkv);
    cudaGetSymbolAddress((void**)&Bproj, g_Bproj);
    cudaGetSymbolAddress((void**)&AO,    g_AO);
    cudaGetSymbolAddress((void**)&qbf,   g_qbf);
    cudaGetSymbolAddress((void**)&kbf,   g_kbf);

    const int AV_SMEM = 8 * 8192 + 8 * 4096;  // 96 KB
    cudaFuncSetAttribute(av_mma_kernel,
                         cudaFuncAttributeMaxDynamicSharedMemorySize, AV_SMEM);

    // 1. input hi/lo splits + mask probe
    convert_all_kernel<<<4097, 128>>>(x, q_w, kv_w, proj_w, mask, Ax, Bqkv, Bproj);

    // 2. fused q/kv projection -> qbf/kbf triples + yvf fp32
    mma_gemm_t<3072, 48, 1><<<dim3(12, 16), 256>>>(
        Ax, Bqkv, nullptr, yvf, nullptr, 0, 0, 0, qbf, kbf);

    // 3. S = 0.125 * q@k^T per (b,h)
    mma_gemm_t<384, 6, 2><<<dim3(128, 1), 256>>>(
        qbf, kbf, S, nullptr, nullptr, 0, 0, 0, nullptr, nullptr);

    // 4. logits + masked softmax + W (fp32)
    att_kernel<<<kB * kN, 256>>>(S, assign, mask, rel_bias, Wfp);

    // 5. O = W @ yv per (b,h), combo split-K on tensor cores (emits AO triple)
    av_mma_kernel<<<128, 256, AV_SMEM>>>(Wfp, yvf, AO);

    // 6. out-proj: AO @ Bproj^T + bias
    mma_gemm_t<3072, 48, 0><<<dim3(4, 16), 256>>>(
        AO, Bproj, (float*)d_out, (float*)d_out, proj_b, 1 << 30, kC, kC,
        nullptr, nullptr);
}

// round 10
// speedup vs baseline: 1.1362x; 1.0244x over previous
#include <cuda_runtime.h>
#include <cuda_bf16.h>
#include <cstdint>

// Problem dims
constexpr int kB  = 16;
constexpr int kN  = 128;
constexpr int kC  = 512;
constexpr int kH  = 8;
constexpr int kR  = 17;
constexpr int kHD = 64;
constexpr int kBN = kB * kN;    // 2048
constexpr int kKp = 3 * kC;     // 1536 split-K' (c contraction)
constexpr int kKq = 3 * kHD;    // 192 split-K' (d contraction, qk)

// Scratch (device globals; no allocations allowed)
__device__ float g_S[kB * kH * kN * kN];  // 8 MB (pre-scaled by 0.125)
__device__ float g_Wf[kB * kH * kN * kN]; // 8 MB attention weights fp32
__device__ float g_yvf[kB * kH * kN * kHD]; // 4 MB yv fp32 [bh][m][64]
__device__ float g_AsT[kN * kR * kN];     // 1.1 MB A^T fp32 [n][r][128m]
__device__ int   g_mask_mode;
__device__ __nv_bfloat16 g_Ax[kBN * kKp];        // x hi|lo|hi
__device__ __nv_bfloat16 g_Bqkv[kKp * kKp];      // [q_w;kv_w] hi|hi|lo
__device__ __nv_bfloat16 g_Bproj[kC * kKp];      // proj_w hi|hi|lo
__device__ __nv_bfloat16 g_AO[kBN * kKp];        // O hi|lo|hi (av epilogue)
__device__ __nv_bfloat16 g_qbf[kB * kH * kN * kKq]; // q hi|lo|hi per (b,h)
__device__ __nv_bfloat16 g_kbf[kB * kH * kN * kKq]; // k hi|hi|lo per (b,h)

__device__ __forceinline__ float neg_inf() { return __int_as_float(0xFF800000); }

// ===================== baseline-PTX helpers =====================
__device__ __forceinline__ uint32_t smem_u32(const void* p) {
    uint32_t a;
    asm("{ .reg .u64 t; cvta.to.shared.u64 t, %1; cvt.u32.u64 %0, t; }"
        : "=r"(a) : "l"(p));
    return a;
}
__device__ __forceinline__ void cp_async16(uint32_t saddr, const void* gaddr) {
    asm volatile("cp.async.cg.shared.global [%0], [%1], 16;"
                 :: "r"(saddr), "l"(gaddr) : "memory");
}
__device__ __forceinline__ void cp_commit() {
    asm volatile("cp.async.commit_group;" ::: "memory");
}
__device__ __forceinline__ void cp_wait0() {
    asm volatile("cp.async.wait_group 0;" ::: "memory");
}
__device__ __forceinline__ void ldsm_x4(uint32_t* r, uint32_t addr) {
    asm volatile("ldmatrix.sync.aligned.m8n8.x4.shared.b16 {%0,%1,%2,%3}, [%4];"
                 : "=r"(r[0]), "=r"(r[1]), "=r"(r[2]), "=r"(r[3]) : "r"(addr));
}
__device__ __forceinline__ void mma16816(float* d, const uint32_t* a, const uint32_t* b) {
    asm volatile("mma.sync.aligned.m16n8k16.row.col.f32.bf16.bf16.f32 "
                 "{%0,%1,%2,%3}, {%4,%5,%6,%7}, {%8,%9}, {%0,%1,%2,%3};"
                 : "+f"(d[0]), "+f"(d[1]), "+f"(d[2]), "+f"(d[3])
                 : "r"(a[0]), "r"(a[1]), "r"(a[2]), "r"(a[3]),
                   "r"(b[0]), "r"(b[1]));
}
__device__ __forceinline__ uint32_t pack_bf2(__nv_bfloat16 lo, __nv_bfloat16 hi) {
    return ((uint32_t)__bfloat16_as_ushort(hi) << 16) | __bfloat16_as_ushort(lo);
}
__device__ __forceinline__ void sts32(uint32_t addr, uint32_t v) {
    asm volatile("st.shared.b32 [%0], %1;" :: "r"(addr), "r"(v) : "memory");
}
__device__ __forceinline__ void sts64(uint32_t addr, uint32_t v0, uint32_t v1) {
    asm volatile("st.shared.v2.b32 [%0], {%1,%2};" :: "r"(addr), "r"(v0), "r"(v1) : "memory");
}

// ===================== fused converts + mask probe + A-transpose ============
// rb < 4096: hi/lo splits. rb == 4096: mask probe. rb in [4097,4225): A^T.
__global__ __launch_bounds__(128) void convert_all_kernel(
    const float* __restrict__ x, const float* __restrict__ q_w,
    const float* __restrict__ kv_w, const float* __restrict__ proj_w,
    const float* __restrict__ assign, const void* __restrict__ mask,
    __nv_bfloat16* __restrict__ Ax, __nv_bfloat16* __restrict__ Bqkv,
    __nv_bfloat16* __restrict__ Bproj, float* __restrict__ AsTg)
{
    const int rb = blockIdx.x;
    if (rb == 4096) {
        __shared__ int s_not_i32, s_not_f32;
        if (threadIdx.x == 0) { s_not_i32 = 0; s_not_f32 = 0; }
        __syncthreads();
        const unsigned int* w = (const unsigned int*)mask;
        int bad_i = 0, bad_f = 0;
        for (int i = threadIdx.x; i < 544; i += 128) {
            unsigned int v = w[i];
            if (v > 1u) bad_i = 1;
            if (v != 0u && v != 0x3F800000u) bad_f = 1;
        }
        if (bad_i) atomicOr(&s_not_i32, 1);
        if (bad_f) atomicOr(&s_not_f32, 1);
        __syncthreads();
        if (threadIdx.x == 0)
            g_mask_mode = (!s_not_i32) ? 0 : ((!s_not_f32) ? 1 : 2);
        return;
    }
    if (rb >= 4097) {
        // transpose assignment[n]: [128m][17r] -> [17r][128m]
        const int n = rb - 4097;
        __shared__ __align__(16) float At[2176];
        const float* arow = assign + (size_t)n * 2176;
        for (int i = threadIdx.x; i < 544; i += 128)
            *(float4*)&At[i * 4] = *(const float4*)&arow[i * 4];
        __syncthreads();
        float* out = AsTg + (size_t)n * 2176;
        for (int j = threadIdx.x; j < 544; j += 128) {
            const int o = j * 4;
            const int r = o >> 7, m = o & 127;
            float4 v = make_float4(At[m * kR + r], At[(m + 1) * kR + r],
                                   At[(m + 2) * kR + r], At[(m + 3) * kR + r]);
            *(float4*)&out[o] = v;
        }
        return;
    }
    const float* src;
    __nv_bfloat16* dst;
    bool aSide;
    if (rb < 2048)      { src = x + (size_t)rb * kC;             dst = Ax + (size_t)rb * kKp;           aSide = true;  }
    else if (rb < 2560) { int r = rb - 2048; src = q_w + (size_t)r * kC;    dst = Bqkv + (size_t)r * kKp;        aSide = false; }
    else if (rb < 3584) { int r = rb - 2560; src = kv_w + (size_t)r * kC;   dst = Bqkv + (size_t)(kC + r) * kKp; aSide = false; }
    else                { int r = rb - 3584; src = proj_w + (size_t)r * kC; dst = Bproj + (size_t)r * kKp;       aSide = false; }

    const int j0 = threadIdx.x * 4;
    float4 v = *(const float4*)&src[j0];
    float f[4] = {v.x, v.y, v.z, v.w};
    __nv_bfloat16 hi[4], lo[4];
#pragma unroll
    for (int t = 0; t < 4; t++) {
        hi[t] = __float2bfloat16(f[t]);
        lo[t] = __float2bfloat16(f[t] - __bfloat162float(hi[t]));
    }
    uint32_t hp0 = pack_bf2(hi[0], hi[1]), hp1 = pack_bf2(hi[2], hi[3]);
    uint32_t lp0 = pack_bf2(lo[0], lo[1]), lp1 = pack_bf2(lo[2], lo[3]);
    uint32_t* d0 = (uint32_t*)(dst + j0);
    uint32_t* d1 = (uint32_t*)(dst + kC + j0);
    uint32_t* d2 = (uint32_t*)(dst + 2 * kC + j0);
    d0[0] = hp0; d0[1] = hp1;
    if (aSide) { d1[0] = lp0; d1[1] = lp1; d2[0] = hp0; d2[1] = hp1; }
    else       { d1[0] = hp0; d1[1] = hp1; d2[0] = lp0; d2[1] = lp1; }
}

// ===================== templated mma.sync bf16 GEMM =====================
// MODE 0: C0/C1 fp32 split-column output (+bias)
// MODE 1: qkv epilogue -> qbf/kbf triples + yvf fp32 [bh][m][64] (C1 = yvf)
// MODE 2: per-(b,h) qk: S = 0.125 * q@k^T
template<int KBYTES, int NITER, int MODE>
__global__ __launch_bounds__(256) void mma_gemm_t(
    const __nv_bfloat16* __restrict__ A,
    const __nv_bfloat16* __restrict__ Bw,
    float* __restrict__ C0, float* __restrict__ C1,
    const float* __restrict__ bias, int split, int ld0, int ld1,
    __nv_bfloat16* __restrict__ qbf, __nv_bfloat16* __restrict__ kbf)
{
    __shared__ __align__(16) char smem[2][16384];
    const int tid = threadIdx.x;
    const int wid = tid >> 5, lane = tid & 31;
    const int warp_m = wid >> 1, warp_n = wid & 1;

    int m0, n0;
    const char *Ag, *Bg;
    if (MODE == 2) {
        const size_t off = (size_t)blockIdx.x * 128 * KBYTES;
        Ag = (const char*)A + off;
        Bg = (const char*)Bw + off;
        m0 = 0; n0 = 0;
    } else {
        m0 = blockIdx.y * 128; n0 = blockIdx.x * 128;
        Ag = (const char*)A  + (size_t)m0 * KBYTES;
        Bg = (const char*)Bw + (size_t)n0 * KBYTES;
    }

    const int lr = tid >> 2, lc = tid & 3;
    const uint32_t lso  = (uint32_t)(lr * 64 + ((lc ^ (lr & 3)) << 4));
    const uint32_t lso2 = (uint32_t)((lr + 64) * 64 + ((lc ^ ((lr + 64) & 3)) << 4));
    uint32_t sbase = smem_u32(&smem[0][0]);

    auto stage_load = [&](int st, int k0b) {
        uint32_t sA = sbase + st * 16384;
        uint32_t sB = sA + 8192;
        const char* a0 = Ag + (size_t)lr * KBYTES + k0b + lc * 16;
        const char* b0 = Bg + (size_t)lr * KBYTES + k0b + lc * 16;
        cp_async16(sA + lso,  a0);
        cp_async16(sB + lso,  b0);
        cp_async16(sA + lso2, a0 + (size_t)64 * KBYTES);
        cp_async16(sB + lso2, b0 + (size_t)64 * KBYTES);
    };

    float acc[2][8][4];
#pragma unroll
    for (int i = 0; i < 2; i++)
#pragma unroll
        for (int j = 0; j < 8; j++)
#pragma unroll
            for (int t = 0; t < 4; t++) acc[i][j][t] = 0.f;

    stage_load(0, 0);
    cp_commit();

    const int a_row = warp_m * 32 + (lane & 15);
    const int a_chsel = lane >> 4;
    const int b_mi = lane >> 3;
    const int b_row = warp_n * 64 + ((b_mi >> 1) << 3) + (lane & 7);
    const int b_chsel = b_mi & 1;

    for (int it = 0; it < NITER; it++) {
        cp_wait0();
        __syncthreads();
        if (it + 1 < NITER) { stage_load((it + 1) & 1, (it + 1) * 64); cp_commit(); }

        const uint32_t sA = sbase + (it & 1) * 16384;
        const uint32_t sB = sA + 8192;
#pragma unroll
        for (int kk = 0; kk < 2; kk++) {
            uint32_t a[2][4];
#pragma unroll
            for (int i = 0; i < 2; i++) {
                int r = a_row + i * 16;
                int ch = 2 * kk + a_chsel;
                ldsm_x4(a[i], sA + r * 64 + ((ch ^ (r & 3)) << 4));
            }
            uint32_t b[8][2];
#pragma unroll
            for (int g = 0; g < 4; g++) {
                int r = b_row + g * 16;
                int ch = 2 * kk + b_chsel;
                uint32_t rr[4];
                ldsm_x4(rr, sB + r * 64 + ((ch ^ (r & 3)) << 4));
                b[2 * g][0] = rr[0]; b[2 * g][1] = rr[1];
                b[2 * g + 1][0] = rr[2]; b[2 * g + 1][1] = rr[3];
            }
#pragma unroll
            for (int i = 0; i < 2; i++)
#pragma unroll
                for (int j = 0; j < 8; j++)
                    mma16816(acc[i][j], a[i], b[j]);
        }
        __syncthreads();
    }

    const int gq = lane >> 2, t4 = lane & 3;

    if (MODE == 2) {
        float* Sp = C0 + (size_t)blockIdx.x * kN * kN;
#pragma unroll
        for (int i = 0; i < 2; i++) {
#pragma unroll
            for (int j = 0; j < 8; j++) {
                int col = warp_n * 64 + j * 8 + t4 * 2;
                int r0 = warp_m * 32 + i * 16 + gq;
                *(float2*)&Sp[(size_t)r0 * kN + col] =
                    make_float2(acc[i][j][0] * 0.125f, acc[i][j][1] * 0.125f);
                *(float2*)&Sp[(size_t)(r0 + 8) * kN + col] =
                    make_float2(acc[i][j][2] * 0.125f, acc[i][j][3] * 0.125f);
            }
        }
        return;
    }

    if (MODE == 1) {
        auto emit = [&](int row, int colg, float f0, float f1) {
            if (colg < 1024) {
                const bool isQ = colg < 512;
                const int c = isQ ? colg : colg - 512;
                const int h = c >> 6, d = c & 63;
                __nv_bfloat16 h0 = __float2bfloat16(f0);
                __nv_bfloat16 h1 = __float2bfloat16(f1);
                __nv_bfloat16 l0 = __float2bfloat16(f0 - __bfloat162float(h0));
                __nv_bfloat16 l1 = __float2bfloat16(f1 - __bfloat162float(h1));
                uint32_t hp = pack_bf2(h0, h1);
                uint32_t lp = pack_bf2(l0, l1);
                const int bb = row >> 7, nn = row & 127;
                __nv_bfloat16* base = (isQ ? qbf : kbf)
                    + ((size_t)((bb * kH + h) * kN + nn)) * kKq + d;
                *(uint32_t*)(base)       = hp;
                *(uint32_t*)(base + 64)  = isQ ? lp : hp;
                *(uint32_t*)(base + 128) = isQ ? hp : lp;
            } else {
                const int c = colg - 1024;
                const int h = c >> 6, d = c & 63;
                const int bb = row >> 7, m = row & 127;
                *(float2*)&C1[((size_t)((bb * kH + h) * kN + m)) * kHD + d] =
                    make_float2(f0, f1);
            }
        };
#pragma unroll
        for (int i = 0; i < 2; i++) {
#pragma unroll
            for (int j = 0; j < 8; j++) {
                int colg = n0 + warp_n * 64 + j * 8 + t4 * 2;
                int row0 = m0 + warp_m * 32 + i * 16 + gq;
                emit(row0,     colg, acc[i][j][0], acc[i][j][1]);
                emit(row0 + 8, colg, acc[i][j][2], acc[i][j][3]);
            }
        }
        return;
    }

    // MODE 0
#pragma unroll
    for (int i = 0; i < 2; i++) {
#pragma unroll
        for (int j = 0; j < 8; j++) {
            int colg = n0 + warp_n * 64 + j * 8 + t4 * 2;
            float bz0 = bias ? bias[colg]     : 0.f;
            float bz1 = bias ? bias[colg + 1] : 0.f;
            float* Cc; int ldc, cc;
            if (colg < split) { Cc = C0; ldc = ld0; cc = colg; }
            else              { Cc = C1; ldc = ld1; cc = colg - split; }
            int row0 = m0 + warp_m * 32 + i * 16 + gq;
            *(float2*)&Cc[(size_t)row0 * ldc + cc] =
                make_float2(acc[i][j][0] + bz0, acc[i][j][1] + bz1);
            *(float2*)&Cc[(size_t)(row0 + 8) * ldc + cc] =
                make_float2(acc[i][j][2] + bz0, acc[i][j][3] + bz1);
        }
    }
}

// ===================== att v4: warp-collective, no transpose ================
// Block per (b,n). Warp h: register-resident S row, 17 warp dots + shfl.
__global__ __launch_bounds__(256) void att_kernel(
    const float* __restrict__ S, const float* __restrict__ AsTg,
    const void* __restrict__ mask, const float* __restrict__ rel_bias,
    float* __restrict__ Wf)
{
    __shared__ __align__(16) float As[kR * 132];
    __shared__ __align__(16) float Ss[kH * 132];
    __shared__ __align__(16) float Ls[kH * 20];
    __shared__ __align__(16) float Ps[kH * 20];
    __shared__ __align__(16) float rb[136];
    __shared__ __align__(16) int   mk[kR];

    const int t = threadIdx.x, wid = t >> 5, lane = t & 31;
    const int b = blockIdx.x >> 7, n = blockIdx.x & 127;

    // loads (all coalesced)
    {
        const int h = t >> 5, m0 = (t & 31) * 4;
        *(float4*)&Ss[h * 132 + m0] =
            *(const float4*)&S[(((size_t)(b * kH + h)) * kN + n) * kN + m0];
    }
    const float* ag = AsTg + (size_t)n * (kR * kN);
    for (int i = t; i < 544; i += 256) {
        const int r = i >> 5, m0 = (i & 31) * 4;
        *(float4*)&As[r * 132 + m0] = *(const float4*)&ag[r * kN + m0];
    }
    if (t < 136) rb[t] = rel_bias[t];
    if (t < kR) {
        int mode = g_mask_mode;
        int idx = n * kR + t;
        bool m_;
        if (mode == 0)      m_ = ((const int*)mask)[idx] != 0;
        else if (mode == 1) m_ = ((const float*)mask)[idx] != 0.f;
        else                m_ = ((const unsigned char*)mask)[idx] != 0;
        mk[t] = m_ ? 1 : 0;
    }
    __syncthreads();

    // logits: warp wid == head h; 17 warp-collective dots
    {
        const int h = wid;
        float4 sv = *(const float4*)&Ss[h * 132 + lane * 4];
#pragma unroll
        for (int r = 0; r < kR; r++) {
            float4 av = *(const float4*)&As[r * 132 + lane * 4];
            float d = sv.x * av.x + sv.y * av.y + sv.z * av.z + sv.w * av.w;
#pragma unroll
            for (int o = 16; o > 0; o >>= 1)
                d += __shfl_xor_sync(0xFFFFFFFFu, d, o);
            if (lane == 0)
                Ls[h * 20 + r] = mk[r] ? neg_inf() : (d + rb[h * kR + r]);
        }
    }
    __syncthreads();

    // softmax: warp wid == head h, lanes 0..16
    {
        const int h = wid;
        float v = (lane < kR) ? Ls[h * 20 + lane] : neg_inf();
        float mx = v;
#pragma unroll
        for (int o = 16; o > 0; o >>= 1)
            mx = fmaxf(mx, __shfl_xor_sync(0xFFFFFFFFu, mx, o));
        float e = (lane < kR) ? __expf(v - mx) : 0.f;
        float s = e;
#pragma unroll
        for (int o = 16; o > 0; o >>= 1)
            s += __shfl_xor_sync(0xFFFFFFFFu, s, o);
        if (lane < kR) Ps[h * 20 + lane] = e / s;
    }
    __syncthreads();

    // W: thread = (h-group, m); 4 heads per thread
    {
        const int m = t & 127, hg = t >> 7;
        float acc[4] = {0.f, 0.f, 0.f, 0.f};
#pragma unroll
        for (int r = 0; r < kR; r++) {
            float a = As[r * 132 + m];
#pragma unroll
            for (int u = 0; u < 4; u++)
                acc[u] += Ps[(hg * 4 + u) * 20 + r] * a;
        }
#pragma unroll
        for (int u = 0; u < 4; u++)
            Wf[(((size_t)(b * kH + hg * 4 + u)) * kN + n) * kN + m] = acc[u];
    }
}

// ===================== av combo mma: O = W @ yv^T per (b,h) =================
__global__ __launch_bounds__(256) void av_mma_kernel(
    const float* __restrict__ Wf, const float* __restrict__ yvf,
    __nv_bfloat16* __restrict__ AO)
{
    extern __shared__ __align__(16) char dsm[];
    const int tid = threadIdx.x, wid = tid >> 5, lane = tid & 31;
    const int bh = blockIdx.x;
    const int warp_m = wid >> 1, warp_n = wid & 1;
    const uint32_t sbase = smem_u32(dsm);           // A stages: 8 x 8KB
    const uint32_t vbase = sbase + 65536u;          // B stages: 8 x 4KB

    const float* Wb = Wf + (size_t)bh * kN * kN;
    {
        const int mq = tid & 31, r0 = tid >> 5;
#pragma unroll
        for (int i = 0; i < 16; i++) {
            const int row = r0 + 8 * i;
            float4 v = *(const float4*)&Wb[(size_t)row * kN + mq * 4];
            float f[4] = {v.x, v.y, v.z, v.w};
            __nv_bfloat16 hi[4], lo[4];
#pragma unroll
            for (int u = 0; u < 4; u++) {
                hi[u] = __float2bfloat16(f[u]);
                lo[u] = __float2bfloat16(f[u] - __bfloat162float(hi[u]));
            }
            const int m0 = mq * 4;
            const int stage = m0 >> 5;
            const int ch = (m0 & 31) >> 3;
            const int hb = (m0 & 7) >> 2;
            uint32_t addr = sbase + stage * 8192 + row * 64
                          + ((ch ^ (row & 3)) << 4) + hb * 8;
            sts64(addr, pack_bf2(hi[0], hi[1]), pack_bf2(hi[2], hi[3]));
            sts64(addr + 4 * 8192, pack_bf2(lo[0], lo[1]), pack_bf2(lo[2], lo[3]));
        }
    }
    const float* Vb = yvf + (size_t)bh * kN * kHD;
    {
        const int dq = tid & 15, mp0 = tid >> 4;
#pragma unroll
        for (int i = 0; i < 4; i++) {
            const int mp = mp0 + 16 * i;
            const int m0 = 2 * mp;
            float4 v0 = *(const float4*)&Vb[(size_t)m0 * kHD + dq * 4];
            float4 v1 = *(const float4*)&Vb[(size_t)(m0 + 1) * kHD + dq * 4];
            float f0[4] = {v0.x, v0.y, v0.z, v0.w};
            float f1[4] = {v1.x, v1.y, v1.z, v1.w};
            const int stage = m0 >> 5;
            const int ch = (m0 & 31) >> 3;
            const int ob = (m0 & 7) * 2;
#pragma unroll
            for (int u = 0; u < 4; u++) {
                const int row = dq * 4 + u;
                __nv_bfloat16 h0 = __float2bfloat16(f0[u]);
                __nv_bfloat16 h1 = __float2bfloat16(f1[u]);
                __nv_bfloat16 l0 = __float2bfloat16(f0[u] - __bfloat162float(h0));
                __nv_bfloat16 l1 = __float2bfloat16(f1[u] - __bfloat162float(h1));
                uint32_t addr = vbase + stage * 4096 + row * 64
                              + ((ch ^ (row & 3)) << 4) + ob;
                sts32(addr, pack_bf2(h0, h1));
                sts32(addr + 4 * 4096, pack_bf2(l0, l1));
            }
        }
    }
    __syncthreads();

    float acc[2][4][4];
#pragma unroll
    for (int i = 0; i < 2; i++)
#pragma unroll
        for (int j = 0; j < 4; j++)
#pragma unroll
            for (int t = 0; t < 4; t++) acc[i][j][t] = 0.f;

    const int a_row = warp_m * 32 + (lane & 15);
    const int a_chsel = lane >> 4;
    const int b_mi = lane >> 3;
    const int b_row = warp_n * 32 + ((b_mi >> 1) << 3) + (lane & 7);
    const int b_chsel = b_mi & 1;

    const int schedA[12] = {0,1,2,3, 4,5,6,7, 0,1,2,3};
    const int schedB[12] = {0,1,2,3, 0,1,2,3, 4,5,6,7};

#pragma unroll
    for (int it = 0; it < 12; it++) {
        const uint32_t sA = sbase + schedA[it] * 8192;
        const uint32_t sB = vbase + schedB[it] * 4096;
#pragma unroll
        for (int kk = 0; kk < 2; kk++) {
            uint32_t a[2][4];
#pragma unroll
            for (int i = 0; i < 2; i++) {
                int r = a_row + i * 16;
                int ch = 2 * kk + a_chsel;
                ldsm_x4(a[i], sA + r * 64 + ((ch ^ (r & 3)) << 4));
            }
            uint32_t b[4][2];
#pragma unroll
            for (int g = 0; g < 2; g++) {
                int r = b_row + g * 16;
                int ch = 2 * kk + b_chsel;
                uint32_t rr[4];
                ldsm_x4(rr, sB + r * 64 + ((ch ^ (r & 3)) << 4));
                b[2 * g][0] = rr[0]; b[2 * g][1] = rr[1];
                b[2 * g + 1][0] = rr[2]; b[2 * g + 1][1] = rr[3];
            }
#pragma unroll
            for (int i = 0; i < 2; i++)
#pragma unroll
                for (int j = 0; j < 4; j++)
                    mma16816(acc[i][j], a[i], b[j]);
        }
    }

    const int gq = lane >> 2, t4 = lane & 3;
    const int b_ = bh >> 3, h_ = bh & 7;
#pragma unroll
    for (int i = 0; i < 2; i++) {
#pragma unroll
        for (int j = 0; j < 4; j++) {
            const int d = warp_n * 32 + j * 8 + t4 * 2;
            const int c = h_ * kHD + d;
#pragma unroll
            for (int rr = 0; rr < 2; rr++) {
                const int nrow = warp_m * 32 + i * 16 + gq + rr * 8;
                const float f0 = acc[i][j][rr * 2], f1 = acc[i][j][rr * 2 + 1];
                __nv_bfloat16 h0 = __float2bfloat16(f0), h1 = __float2bfloat16(f1);
                __nv_bfloat16 l0 = __float2bfloat16(f0 - __bfloat162float(h0));
                __nv_bfloat16 l1 = __float2bfloat16(f1 - __bfloat162float(h1));
                __nv_bfloat16* base = AO + (size_t)(b_ * kN + nrow) * kKp + c;
                *(uint32_t*)(base)        = pack_bf2(h0, h1);
                *(uint32_t*)(base + 512)  = pack_bf2(l0, l1);
                *(uint32_t*)(base + 1024) = pack_bf2(h0, h1);
            }
        }
    }
}

// ===================== launch =====================
extern "C" void kernel_launch(void* const* d_in, const int* in_sizes, int n_in,
                              void* d_out, int out_size)
{
    const float* x        = (const float*)d_in[0];
    const float* assign   = (const float*)d_in[1];
    const void*  mask     = d_in[2];
    const float* q_w      = (const float*)d_in[3];
    const float* kv_w     = (const float*)d_in[4];
    const float* rel_bias = (const float*)d_in[5];
    const float* proj_w   = (const float*)d_in[6];
    const float* proj_b   = (const float*)d_in[7];

    float *S, *Wfp, *yvf, *AsTg;
    __nv_bfloat16 *Ax, *Bqkv, *Bproj, *AO, *qbf, *kbf;
    cudaGetSymbolAddress((void**)&S,    g_S);
    cudaGetSymbolAddress((void**)&Wfp,  g_Wf);
    cudaGetSymbolAddress((void**)&yvf,  g_yvf);
    cudaGetSymbolAddress((void**)&AsTg, g_AsT);
    cudaGetSymbolAddress((void**)&Ax,    g_Ax);
    cudaGetSymbolAddress((void**)&Bqkv,  g_Bqkv);
    cudaGetSymbolAddress((void**)&Bproj, g_Bproj);
    cudaGetSymbolAddress((void**)&AO,    g_AO);
    cudaGetSymbolAddress((void**)&qbf,   g_qbf);
    cudaGetSymbolAddress((void**)&kbf,   g_kbf);

    const int AV_SMEM = 8 * 8192 + 8 * 4096;  // 96 KB
    cudaFuncSetAttribute(av_mma_kernel,
                         cudaFuncAttributeMaxDynamicSharedMemorySize, AV_SMEM);

    // 1. input hi/lo splits + mask probe + A transpose
    convert_all_kernel<<<4225, 128>>>(x, q_w, kv_w, proj_w, assign, mask,
                                      Ax, Bqkv, Bproj, AsTg);

    // 2. fused q/kv projection -> qbf/kbf triples + yvf fp32
    mma_gemm_t<3072, 48, 1><<<dim3(12, 16), 256>>>(
        Ax, Bqkv, nullptr, yvf, nullptr, 0, 0, 0, qbf, kbf);

    // 3. S = 0.125 * q@k^T per (b,h)
    mma_gemm_t<384, 6, 2><<<dim3(128, 1), 256>>>(
        qbf, kbf, S, nullptr, nullptr, 0, 0, 0, nullptr, nullptr);

    // 4. logits + masked softmax + W (fp32), warp-collective
    att_kernel<<<kB * kN, 256>>>(S, AsTg, mask, rel_bias, Wfp);

    // 5. O = W @ yv per (b,h), combo split-K on tensor cores (emits AO triple)
    av_mma_kernel<<<128, 256, AV_SMEM>>>(Wfp, yvf, AO);

    // 6. out-proj: AO @ Bproj^T + bias
    mma_gemm_t<3072, 48, 0><<<dim3(4, 16), 256>>>(
        AO, Bproj, (float*)d_out, (float*)d_out, proj_b, 1 << 30, kC, kC,
        nullptr, nullptr);
}